// round 1
// baseline (speedup 1.0000x reference)
#include <cuda_runtime.h>

// NeuralODE: RNN encoder (reverse scan) -> z0 -> RK4 ODE scan -> fused decoder.
// B=4096, T=512, OBS=2, LAT=4, NH=20, RNNH=25.
//
// Output layout (flat float, concatenated in reference return order):
//   pred_x  [B,T,OBS]   at 0
//   z0      [B,LAT]     at B*T*OBS
//   qz0_mean[B,LAT]     next
//   qz0_logvar[B,LAT]   next

#define BD   4096
#define TD   512
#define OBSD 2
#define LATD 4
#define NHD  20
#define RNNHD 25

#define OFF_Z0   (BD * TD * OBSD)
#define OFF_MEAN (OFF_Z0 + BD * LATD)
#define OFF_LV   (OFF_MEAN + BD * LATD)

__device__ float g_z0[BD * LATD];

__device__ __forceinline__ float fast_tanh(float x) {
    // tanh(x) = 1 - 2/(exp(2x)+1); exact at +-inf, ~1e-6 rel err typical
    float e = __expf(2.0f * x);
    return 1.0f - __fdividef(2.0f, e + 1.0f);
}

__device__ __forceinline__ float elu1(float x) {
    float e = __expf(x) - 1.0f;
    return x > 0.0f ? x : e;
}

// ---------------------------------------------------------------------------
// RNN kernel: 8 threads per batch. Each thread owns 4 of 32 (zero-padded)
// hidden outputs; i2h weights live in registers (27 float4 = 108 regs).
// h values exchanged within the 8-lane group via shfl.
// ---------------------------------------------------------------------------
__global__ __launch_bounds__(256) void rnn_kernel(
    const float* __restrict__ trajs,   // [B,T,OBS]
    const float* __restrict__ eps,     // [B,LAT]
    const float* __restrict__ i2h_w,   // [27,25]
    const float* __restrict__ i2h_b,   // [25]
    const float* __restrict__ h2o_w,   // [25,8]
    const float* __restrict__ h2o_b,   // [8]
    float* __restrict__ out)
{
    __shared__ float sw[27 * 32];   // padded weight matrix [k][j], j padded 25->32
    __shared__ float sb[32];        // padded bias
    __shared__ float sow[RNNHD * 8];
    __shared__ float sob[8];

    int tid = threadIdx.x;
    for (int i = tid; i < 27 * 32; i += blockDim.x) sw[i] = 0.0f;
    if (tid < 32) sb[tid] = 0.0f;
    __syncthreads();
    for (int i = tid; i < 27 * 25; i += blockDim.x) {
        int r = i / 25, c = i % 25;
        sw[r * 32 + c] = i2h_w[i];
    }
    if (tid < 25) sb[tid] = i2h_b[tid];
    for (int i = tid; i < RNNHD * 8; i += blockDim.x) sow[i] = h2o_w[i];
    if (tid < 8) sob[tid] = h2o_b[tid];
    __syncthreads();

    int gt   = blockIdx.x * blockDim.x + tid;
    int b    = gt >> 3;
    int sub  = gt & 7;
    int lane = tid & 31;
    int base = lane & ~7;   // first lane of this batch's 8-lane group
    int j0   = sub * 4;

    // per-thread weight slice in registers
    float4 w[27];
#pragma unroll
    for (int k = 0; k < 27; k++)
        w[k] = *reinterpret_cast<const float4*>(&sw[k * 32 + j0]);
    float4 bias = *reinterpret_cast<const float4*>(&sb[j0]);

    float hr[4] = {0.0f, 0.0f, 0.0f, 0.0f};

    const float2* xp = reinterpret_cast<const float2*>(trajs) + (size_t)b * TD;
    float2 xc = xp[TD - 1];

    for (int t = TD - 1; t >= 0; --t) {
        float2 xn = (t > 0) ? xp[t - 1] : make_float2(0.0f, 0.0f);

        float a[4];
        a[0] = bias.x; a[1] = bias.y; a[2] = bias.z; a[3] = bias.w;
        // k = 0,1 : x inputs
        a[0] = fmaf(xc.x, w[0].x, a[0]); a[1] = fmaf(xc.x, w[0].y, a[1]);
        a[2] = fmaf(xc.x, w[0].z, a[2]); a[3] = fmaf(xc.x, w[0].w, a[3]);
        a[0] = fmaf(xc.y, w[1].x, a[0]); a[1] = fmaf(xc.y, w[1].y, a[1]);
        a[2] = fmaf(xc.y, w[1].z, a[2]); a[3] = fmaf(xc.y, w[1].w, a[3]);
        // k = 2..26 : previous h (owned by lane base + (k-2)/4, slot (k-2)%4)
#pragma unroll
        for (int k = 0; k < RNNHD; k++) {
            float hv = __shfl_sync(0xffffffffu, hr[k & 3], base + (k >> 2));
            const float4 wk = w[k + 2];
            a[0] = fmaf(hv, wk.x, a[0]);
            a[1] = fmaf(hv, wk.y, a[1]);
            a[2] = fmaf(hv, wk.z, a[2]);
            a[3] = fmaf(hv, wk.w, a[3]);
        }
#pragma unroll
        for (int i = 0; i < 4; i++) hr[i] = fast_tanh(a[i]);
        xc = xn;
    }

    // h2o: thread computes out[sub] (sub in 0..7)
    float oacc = sob[sub];
#pragma unroll
    for (int k = 0; k < RNNHD; k++) {
        float hv = __shfl_sync(0xffffffffu, hr[k & 3], base + (k >> 2));
        oacc = fmaf(hv, sow[k * 8 + sub], oacc);
    }
    // logvar for lanes sub<4 comes from lane+4
    float lv = __shfl_sync(0xffffffffu, oacc, lane + 4);

    if (sub < 4) {
        float mean = oacc;
        float z0   = eps[b * LATD + sub] * __expf(0.5f * lv) + mean;
        out[OFF_MEAN + b * LATD + sub] = mean;
        out[OFF_Z0   + b * LATD + sub] = z0;
        g_z0[b * LATD + sub] = z0;
    } else {
        out[OFF_LV + b * LATD + (sub - 4)] = oacc;
    }
}

// ---------------------------------------------------------------------------
// ODE kernel: 4 threads per batch, each owns 5 of 20 hidden units (exact).
// f2 weights (20x5) + bias in registers; f1/f3/decoder weights in SMEM
// (uniform broadcast loads). z replicated in all 4 lanes via butterfly
// reductions -> no divergence, every lane steps RK4 identically.
// Decoder fused: writes pred_x[b][t] each step.
// ---------------------------------------------------------------------------
__global__ __launch_bounds__(128) void ode_kernel(
    const float* __restrict__ ts,
    const float* __restrict__ f1_w, const float* __restrict__ f1_b,
    const float* __restrict__ f2_w, const float* __restrict__ f2_b,
    const float* __restrict__ f3_w, const float* __restrict__ f3_b,
    const float* __restrict__ d1_w, const float* __restrict__ d1_b,
    const float* __restrict__ d2_w, const float* __restrict__ d2_b,
    float* __restrict__ out)
{
    __shared__ float sts[TD];
    __shared__ float sf1w[4 * NHD], sf1b[NHD];
    __shared__ float sf3w[NHD * 4], sf3b[4];
    __shared__ float sd1w[4 * NHD], sd1b[NHD];
    __shared__ float sd2w[NHD * 2], sd2b[2];

    int tid = threadIdx.x;
    for (int i = tid; i < TD; i += blockDim.x) sts[i] = ts[i];
    for (int i = tid; i < 4 * NHD; i += blockDim.x) { sf1w[i] = f1_w[i]; sd1w[i] = d1_w[i]; }
    for (int i = tid; i < NHD * 4; i += blockDim.x) sf3w[i] = f3_w[i];
    for (int i = tid; i < NHD * 2; i += blockDim.x) sd2w[i] = d2_w[i];
    for (int i = tid; i < NHD; i += blockDim.x) { sf1b[i] = f1_b[i]; sd1b[i] = d1_b[i]; }
    if (tid < 4) sf3b[tid] = f3_b[tid];
    if (tid < 2) sd2b[tid] = d2_b[tid];
    __syncthreads();

    int gt   = blockIdx.x * blockDim.x + tid;
    int b    = gt >> 2;
    int sub  = gt & 3;
    int lane = tid & 31;
    int base = lane & ~3;
    int j0   = sub * 5;

    // f2 slice in registers: w2[k][i] = f2_w[k][j0+i]
    float w2[NHD][5];
    float b2[5];
#pragma unroll
    for (int k = 0; k < NHD; k++)
#pragma unroll
        for (int i = 0; i < 5; i++)
            w2[k][i] = f2_w[k * NHD + j0 + i];
#pragma unroll
    for (int i = 0; i < 5; i++) b2[i] = f2_b[j0 + i];

    float z[4];
    {
        float4 zz = *reinterpret_cast<const float4*>(&g_z0[b * LATD]);
        z[0] = zz.x; z[1] = zz.y; z[2] = zz.z; z[3] = zz.w;
    }

    // f(z) -> fo, replicated across the 4-lane group
    auto feval = [&](const float* zin, float* fo) {
        float u1o[5];
#pragma unroll
        for (int i = 0; i < 5; i++) {
            float a = sf1b[j0 + i];
#pragma unroll
            for (int k = 0; k < 4; k++)
                a = fmaf(zin[k], sf1w[k * NHD + j0 + i], a);
            u1o[i] = elu1(a);
        }
        float u1[NHD];
#pragma unroll
        for (int k = 0; k < NHD; k++)
            u1[k] = __shfl_sync(0xffffffffu, u1o[k % 5], base + k / 5);
        float u2o[5];
#pragma unroll
        for (int i = 0; i < 5; i++) {
            float a = b2[i];
#pragma unroll
            for (int k = 0; k < NHD; k++)
                a = fmaf(u1[k], w2[k][i], a);
            u2o[i] = elu1(a);
        }
#pragma unroll
        for (int o = 0; o < 4; o++) {
            float p = 0.0f;
#pragma unroll
            for (int i = 0; i < 5; i++)
                p = fmaf(u2o[i], sf3w[(j0 + i) * 4 + o], p);
            p += __shfl_xor_sync(0xffffffffu, p, 1);
            p += __shfl_xor_sync(0xffffffffu, p, 2);
            fo[o] = p + sf3b[o];
        }
    };

    // decoder for one timestep, writes pred_x[b][t][0..1]
    auto decode_write = [&](const float* zin, int t) {
        float p0 = 0.0f, p1 = 0.0f;
#pragma unroll
        for (int i = 0; i < 5; i++) {
            int j = j0 + i;
            float a = sd1b[j];
#pragma unroll
            for (int k = 0; k < 4; k++)
                a = fmaf(zin[k], sd1w[k * NHD + j], a);
            a = fmaxf(a, 0.0f);
            p0 = fmaf(a, sd2w[j * 2 + 0], p0);
            p1 = fmaf(a, sd2w[j * 2 + 1], p1);
        }
        p0 += __shfl_xor_sync(0xffffffffu, p0, 1);
        p0 += __shfl_xor_sync(0xffffffffu, p0, 2);
        p1 += __shfl_xor_sync(0xffffffffu, p1, 1);
        p1 += __shfl_xor_sync(0xffffffffu, p1, 2);
        if (sub == 0) {
            float2 v = make_float2(p0 + sd2b[0], p1 + sd2b[1]);
            *reinterpret_cast<float2*>(&out[((size_t)b * TD + t) * OBSD]) = v;
        }
    };

    decode_write(z, 0);

    for (int step = 0; step < TD - 1; ++step) {
        float dt  = sts[step + 1] - sts[step];
        float hdt = 0.5f * dt;
        float k1[4], k2[4], k3[4], k4[4], zt[4];

        feval(z, k1);
#pragma unroll
        for (int c = 0; c < 4; c++) zt[c] = fmaf(hdt, k1[c], z[c]);
        feval(zt, k2);
#pragma unroll
        for (int c = 0; c < 4; c++) zt[c] = fmaf(hdt, k2[c], z[c]);
        feval(zt, k3);
#pragma unroll
        for (int c = 0; c < 4; c++) zt[c] = fmaf(dt, k3[c], z[c]);
        feval(zt, k4);

        float s = dt * (1.0f / 6.0f);
#pragma unroll
        for (int c = 0; c < 4; c++)
            z[c] = fmaf(s, k1[c] + 2.0f * (k2[c] + k3[c]) + k4[c], z[c]);

        decode_write(z, step + 1);
    }
}

extern "C" void kernel_launch(void* const* d_in, const int* in_sizes, int n_in,
                              void* d_out, int out_size)
{
    (void)in_sizes; (void)n_in; (void)out_size;
    const float* trajs = (const float*)d_in[0];
    const float* ts    = (const float*)d_in[1];
    const float* eps   = (const float*)d_in[2];
    const float* i2h_w = (const float*)d_in[3];
    const float* i2h_b = (const float*)d_in[4];
    const float* h2o_w = (const float*)d_in[5];
    const float* h2o_b = (const float*)d_in[6];
    const float* f1_w  = (const float*)d_in[7];
    const float* f1_b  = (const float*)d_in[8];
    const float* f2_w  = (const float*)d_in[9];
    const float* f2_b  = (const float*)d_in[10];
    const float* f3_w  = (const float*)d_in[11];
    const float* f3_b  = (const float*)d_in[12];
    const float* d1_w  = (const float*)d_in[13];
    const float* d1_b  = (const float*)d_in[14];
    const float* d2_w  = (const float*)d_in[15];
    const float* d2_b  = (const float*)d_in[16];
    float* out = (float*)d_out;

    // RNN: 4096 batches * 8 threads = 32768
    rnn_kernel<<<128, 256>>>(trajs, eps, i2h_w, i2h_b, h2o_w, h2o_b, out);
    // ODE+decode: 4096 batches * 4 threads = 16384
    ode_kernel<<<128, 128>>>(ts, f1_w, f1_b, f2_w, f2_b, f3_w, f3_b,
                             d1_w, d1_b, d2_w, d2_b, out);
}